// round 6
// baseline (speedup 1.0000x reference)
#include <cuda_runtime.h>
#include <cuda_fp16.h>

// Problem constants (fixed by the reference):
// B=4, N=8, H=512, W=512, C=65536, SCALING=10, EPS=1e-10, ITERS=17
// attrs layout: [bbox(4), area(1), angle(1), pca_big(1), pca_small(1), hu(7)] = 15 cols
#define NB 4
#define NN 8
#define NC 65536
#define NATTR 15
#define TOT (NB * NN * NC)        // 2,097,152 elements
#define NPIX (NB * NN * 512 * 512)
#define EPSF 1e-10f
#define CK 16384                  // smem chunk size -> 4 chunks per row
#define CT 1024                   // fused kernel threads
#define GSLICE 4                  // gather slices per row -> 128 blocks, 1 wave

// Packed state: low 32b = float s (partial ancestor sum), high 32b = int p.
__device__ unsigned long long g_sp[TOT];            // 16 MB
__device__ __align__(16) __half g_val[TOT];         // 4 MB final values (*0.1, fp16)

__device__ __forceinline__ unsigned long long pack_sp(float s, int p) {
    return (unsigned long long)(unsigned int)__float_as_int(s)
         | ((unsigned long long)(unsigned int)p << 32);
}
__device__ __forceinline__ float sp_s(unsigned long long v) {
    return __int_as_float((int)(unsigned int)v);
}
__device__ __forceinline__ int sp_p(unsigned long long v) {
    return (int)(v >> 32);
}

// ---------------------------------------------------------------------------
// Phase 1 (fused): score + in-smem chunk compression.
// Block owns CK=16384 elements. Tiled attrs staging (60 KB) + packed state
// array (128 KB) in 188 KB dynamic smem. Scores are written directly into
// smem (no g_sp round trip), then racy-but-untorn 8B pointer doubling runs
// until every pointer escapes the chunk. parent[i] < i guarantees
// termination; post-condition: residual cross-chunk depth <= 3.
// ---------------------------------------------------------------------------
__global__ void __launch_bounds__(CT) score_chunk_kernel(
    const float* __restrict__ diff, const float* __restrict__ attrs,
    const float* __restrict__ weight, const float* __restrict__ bias,
    const int* __restrict__ parent)
{
    extern __shared__ unsigned long long sp[];      // [CK] packed state
    float* sa = (float*)(sp + CK);                  // [CT*NATTR] attrs staging

    const int gbase = blockIdx.x * CK;
    const int cbase = gbase & (NC - 1);             // row-local chunk base
    const int clim  = cbase + CK;
    const int n = (gbase >> 16) & (NN - 1);         // row's N index (constant)

    float wgr[17];
    #pragma unroll
    for (int k = 0; k < 17; k++) wgr[k] = __ldg(&weight[n * 17 + k]);
    const float bs = __ldg(&bias[n]);

    // --- scoring, tile by tile ---
    for (int t = 0; t < CK / CT; t++) {
        const int base = gbase + t * CT;
        const float4* ap = (const float4*)(attrs + (size_t)base * NATTR);
        for (int k = threadIdx.x; k < CT * NATTR / 4; k += CT)
            ((float4*)sa)[k] = ap[k];
        __syncthreads();

        const float* f = &sa[threadIdx.x * NATTR];
        // feats: [bbox0..3, log(area), signed-log f[6..14] (9), lshape, cos, sin]
        float logit = bs;
        logit += f[0] * wgr[0] + f[1] * wgr[1] + f[2] * wgr[2] + f[3] * wgr[3];
        logit += logf(f[4]) * wgr[4];
        #pragma unroll
        for (int k = 0; k < 9; k++) {
            float x = f[6 + k];
            float sg = (float)((x > 0.0f) - (x < 0.0f));
            logit += sg * logf(fabsf(x) + EPSF) * wgr[5 + k];
        }
        logit += (sqrtf(f[7]) / (sqrtf(f[6]) + EPSF)) * wgr[14];
        float sn, cs;
        sincosf(f[5], &sn, &cs);
        logit += cs * wgr[15] + sn * wgr[16];

        const float score = 1.0f / (1.0f + expf(-logit));
        const int idx = base + threadIdx.x;
        sp[idx - gbase] = pack_sp(__ldg(&diff[idx]) * score, __ldg(&parent[idx]));
        __syncthreads();
    }

    // --- in-smem pointer doubling until all pointers escape the chunk ---
    for (;;) {
        int changed = 0;
        #pragma unroll
        for (int j = 0; j < CK / CT; j++) {
            const int e = threadIdx.x + j * CT;
            unsigned long long v = sp[e];
            int p = sp_p(v);
            if (p >= cbase && p < clim) {           // still in-chunk (excludes NC)
                unsigned long long q = sp[p - cbase];
                sp[e] = pack_sp(sp_s(v) + sp_s(q), sp_p(q));
                changed = 1;
            }
        }
        if (!__syncthreads_or(changed)) break;
    }

    for (int j = threadIdx.x; j < CK / 2; j += CT)
        ((ulonglong2*)&g_sp[gbase])[j] = ((const ulonglong2*)sp)[j];
}

// ---------------------------------------------------------------------------
// Phase 2: extract with bounded chain walk (depth <= 3 after chunking).
// 4 lanes per thread for ILP; folds 1/SCALING; writes compacted fp16 values.
// ---------------------------------------------------------------------------
__global__ void __launch_bounds__(256) extract_kernel() {
    const int t = blockIdx.x * 256 + threadIdx.x;
    const int e0 = t * 4;
    const int rowbase = e0 & ~(NC - 1);             // 4 consecutive elems share row
    ulonglong2 a = __ldcg((const ulonglong2*)&g_sp[e0]);
    ulonglong2 b = __ldcg((const ulonglong2*)&g_sp[e0 + 2]);

    float s0 = sp_s(a.x), s1 = sp_s(a.y), s2 = sp_s(b.x), s3 = sp_s(b.y);
    int   p0 = sp_p(a.x), p1 = sp_p(a.y), p2 = sp_p(b.x), p3 = sp_p(b.y);

    #pragma unroll
    for (int it = 0; it < 3; it++) {
        unsigned long long q0 = (p0 != NC) ? __ldcg(&g_sp[rowbase + p0]) : 0ull;
        unsigned long long q1 = (p1 != NC) ? __ldcg(&g_sp[rowbase + p1]) : 0ull;
        unsigned long long q2 = (p2 != NC) ? __ldcg(&g_sp[rowbase + p2]) : 0ull;
        unsigned long long q3 = (p3 != NC) ? __ldcg(&g_sp[rowbase + p3]) : 0ull;
        if (p0 != NC) { s0 += sp_s(q0); p0 = sp_p(q0); }
        if (p1 != NC) { s1 += sp_s(q1); p1 = sp_p(q1); }
        if (p2 != NC) { s2 += sp_s(q2); p2 = sp_p(q2); }
        if (p3 != NC) { s3 += sp_s(q3); p3 = sp_p(q3); }
    }

    __half2 h01 = __floats2half2_rn(s0 * 0.1f, s1 * 0.1f);
    __half2 h23 = __floats2half2_rn(s2 * 0.1f, s3 * 0.1f);
    uint2 o;
    o.x = *(unsigned int*)&h01;
    o.y = *(unsigned int*)&h23;
    ((uint2*)g_val)[t] = o;
}

// ---------------------------------------------------------------------------
// Phase 3: smem-windowed gather. One block per (row, slice); the full
// 65536-entry fp16 value window (128 KB) staged in dynamic smem, pixel
// gathers become LDS. 128 blocks = one full wave; 1024 threads for latency
// hiding (32 warps/SM).
// ---------------------------------------------------------------------------
__global__ void __launch_bounds__(1024) gather_kernel(
    const int* __restrict__ pix2cc, float* __restrict__ out)
{
    extern __shared__ __half sv[];
    const int row = blockIdx.x >> 2;                // GSLICE = 4
    const int pbase = blockIdx.x << 16;             // 65536 pixels per block

    const uint4* vals = (const uint4*)(g_val + (row << 16));
    #pragma unroll
    for (int i = threadIdx.x; i < NC * 2 / 16; i += 1024)
        ((uint4*)sv)[i] = __ldcg(&vals[i]);
    __syncthreads();

    const int4* pc = (const int4*)(pix2cc + pbase);
    float4* op = (float4*)(out + pbase);
    #pragma unroll
    for (int i = threadIdx.x; i < 65536 / 4; i += 1024) {
        const int4 cc = __ldg(&pc[i]);
        float4 o;
        o.x = __half2float(sv[cc.x]);
        o.y = __half2float(sv[cc.y]);
        o.z = __half2float(sv[cc.z]);
        o.w = __half2float(sv[cc.w]);
        op[i] = o;
    }
}

// ---------------------------------------------------------------------------
extern "C" void kernel_launch(void* const* d_in, const int* in_sizes, int n_in,
                              void* d_out, int out_size) {
    const float* diff   = (const float*)d_in[0];
    const float* attrs  = (const float*)d_in[1];
    const float* weight = (const float*)d_in[2];
    const float* bias   = (const float*)d_in[3];
    const int*   parent = (const int*)d_in[4];
    const int*   pix2cc = (const int*)d_in[5];
    float* out = (float*)d_out;

    const int fused_smem  = CK * 8 + CT * NATTR * 4;  // 128 KB + 60 KB = 188 KB
    const int gather_smem = NC * 2;                   // 128 KB
    cudaFuncSetAttribute(score_chunk_kernel,
                         cudaFuncAttributeMaxDynamicSharedMemorySize, fused_smem);
    cudaFuncSetAttribute(gather_kernel,
                         cudaFuncAttributeMaxDynamicSharedMemorySize, gather_smem);

    score_chunk_kernel<<<TOT / CK, CT, fused_smem>>>(diff, attrs, weight, bias, parent);
    extract_kernel<<<TOT / 1024, 256>>>();
    gather_kernel<<<NB * NN * GSLICE, 1024, gather_smem>>>(pix2cc, out);
}

// round 7
// speedup vs baseline: 1.4364x; 1.4364x over previous
#include <cuda_runtime.h>
#include <cuda_fp16.h>

// Problem constants (fixed by the reference):
// B=4, N=8, H=512, W=512, C=65536, SCALING=10, EPS=1e-10, ITERS=17
// attrs layout: [bbox(4), area(1), angle(1), pca_big(1), pca_small(1), hu(7)] = 15 cols
#define NB 4
#define NN 8
#define NC 65536
#define NATTR 15
#define TOT (NB * NN * NC)        // 2,097,152 elements
#define NPIX (NB * NN * 512 * 512)
#define EPSF 1e-10f
#define CK 8192                   // smem chunk size -> 8 chunks per row, 64 KB smem
#define CT 512                    // chunk kernel threads (3 CTAs/SM resident)
#define GSLICE 8                  // gather slices per row (256 blocks of 512)

// Packed state: low 32b = float s (partial ancestor sum), high 32b = int p.
__device__ unsigned long long g_sp[TOT];            // 16 MB
__device__ __align__(16) __half g_val[TOT];         // 4 MB final values (*0.1, fp16)

__device__ __forceinline__ unsigned long long pack_sp(float s, int p) {
    return (unsigned long long)(unsigned int)__float_as_int(s)
         | ((unsigned long long)(unsigned int)p << 32);
}
__device__ __forceinline__ float sp_s(unsigned long long v) {
    return __int_as_float((int)(unsigned int)v);
}
__device__ __forceinline__ int sp_p(unsigned long long v) {
    return (int)(v >> 32);
}

// ---------------------------------------------------------------------------
// Phase 1: w = diff * sigmoid(_log_scaling(attrs) . weight[n] + bias[n]);
// init packed state {w, parent}. attrs staged to smem via float4.
// Full-occupancy streaming kernel (proven ~22us, near DRAM floor).
// ---------------------------------------------------------------------------
__global__ void __launch_bounds__(256) score_kernel(
    const float* __restrict__ diff, const float* __restrict__ attrs,
    const float* __restrict__ weight, const float* __restrict__ bias,
    const int* __restrict__ parent)
{
    __shared__ float sa[256 * NATTR];
    const int base = blockIdx.x * 256;
    const float4* ap = (const float4*)(attrs + (size_t)base * NATTR);
    #pragma unroll
    for (int k = threadIdx.x; k < 256 * NATTR / 4; k += 256)
        ((float4*)sa)[k] = ap[k];
    __syncthreads();

    const int idx = base + threadIdx.x;
    const float* f = &sa[threadIdx.x * NATTR];
    const int n = (idx >> 16) & (NN - 1);      // all 256 elems share one n
    const float* wg = weight + n * 17;

    // feats: [bbox0..3, log(area), signed-log f[6..14] (9), lshape, cos, sin]
    float logit = bias[n];
    logit += f[0] * wg[0] + f[1] * wg[1] + f[2] * wg[2] + f[3] * wg[3];
    logit += logf(f[4]) * wg[4];
    #pragma unroll
    for (int k = 0; k < 9; k++) {
        float x = f[6 + k];
        float sg = (float)((x > 0.0f) - (x < 0.0f));
        logit += sg * logf(fabsf(x) + EPSF) * wg[5 + k];
    }
    logit += (sqrtf(f[7]) / (sqrtf(f[6]) + EPSF)) * wg[14];
    float sn, cs;
    sincosf(f[5], &sn, &cs);
    logit += cs * wg[15] + sn * wg[16];

    const float score = 1.0f / (1.0f + expf(-logit));
    g_sp[idx] = pack_sp(diff[idx] * score, parent[idx]);
}

// ---------------------------------------------------------------------------
// Phase 2a: in-smem chunk compression, CK=8192 (64 KB dynamic smem,
// up to 3 CTAs/SM -> full-device residency). Racy-but-untorn 8B smem
// doubling until every pointer escapes the chunk. parent[i] < i guarantees
// termination. Post-condition: pointers target strictly lower chunks of the
// same row (or NC); with 8 chunks/row, residual cross-chunk depth <= 7.
// ---------------------------------------------------------------------------
__global__ void __launch_bounds__(CT) chunk_kernel() {
    extern __shared__ unsigned long long sp[];
    const int gbase = blockIdx.x * CK;
    const int cbase = gbase & (NC - 1);        // row-local chunk base
    const int clim  = cbase + CK;

    for (int j = threadIdx.x; j < CK / 2; j += CT)
        ((ulonglong2*)sp)[j] = ((const ulonglong2*)&g_sp[gbase])[j];
    __syncthreads();

    for (;;) {
        int changed = 0;
        #pragma unroll
        for (int j = 0; j < CK / CT; j++) {
            const int e = threadIdx.x + j * CT;
            unsigned long long v = sp[e];
            int p = sp_p(v);
            if (p >= cbase && p < clim) {       // still in-chunk (excludes NC)
                unsigned long long q = sp[p - cbase];
                sp[e] = pack_sp(sp_s(v) + sp_s(q), sp_p(q));
                changed = 1;
            }
        }
        if (!__syncthreads_or(changed)) break;
    }

    for (int j = threadIdx.x; j < CK / 2; j += CT)
        ((ulonglong2*)&g_sp[gbase])[j] = ((const ulonglong2*)sp)[j];
}

// ---------------------------------------------------------------------------
// Phase 2b: extract via bounded chain walk (depth <= 7, avg ~2). g_sp is
// read-only here, so a variable-trip walk is safe. 4 lanes/thread for ILP;
// folds 1/SCALING; writes compacted fp16 values.
// ---------------------------------------------------------------------------
__global__ void __launch_bounds__(256) extract_kernel() {
    const int t = blockIdx.x * 256 + threadIdx.x;
    const int e0 = t * 4;
    const int rowbase = e0 & ~(NC - 1);        // 4 consecutive elems share row
    ulonglong2 a = __ldcg((const ulonglong2*)&g_sp[e0]);
    ulonglong2 b = __ldcg((const ulonglong2*)&g_sp[e0 + 2]);

    float s0 = sp_s(a.x), s1 = sp_s(a.y), s2 = sp_s(b.x), s3 = sp_s(b.y);
    int   p0 = sp_p(a.x), p1 = sp_p(a.y), p2 = sp_p(b.x), p3 = sp_p(b.y);

    while ((p0 != NC) | (p1 != NC) | (p2 != NC) | (p3 != NC)) {
        unsigned long long q0 = (p0 != NC) ? __ldcg(&g_sp[rowbase + p0]) : 0ull;
        unsigned long long q1 = (p1 != NC) ? __ldcg(&g_sp[rowbase + p1]) : 0ull;
        unsigned long long q2 = (p2 != NC) ? __ldcg(&g_sp[rowbase + p2]) : 0ull;
        unsigned long long q3 = (p3 != NC) ? __ldcg(&g_sp[rowbase + p3]) : 0ull;
        if (p0 != NC) { s0 += sp_s(q0); p0 = sp_p(q0); }
        if (p1 != NC) { s1 += sp_s(q1); p1 = sp_p(q1); }
        if (p2 != NC) { s2 += sp_s(q2); p2 = sp_p(q2); }
        if (p3 != NC) { s3 += sp_s(q3); p3 = sp_p(q3); }
    }

    __half2 h01 = __floats2half2_rn(s0 * 0.1f, s1 * 0.1f);
    __half2 h23 = __floats2half2_rn(s2 * 0.1f, s3 * 0.1f);
    uint2 o;
    o.x = *(unsigned int*)&h01;
    o.y = *(unsigned int*)&h23;
    ((uint2*)g_val)[t] = o;
}

// ---------------------------------------------------------------------------
// Phase 3: smem-windowed gather (proven 16.3us). One block per (row, slice);
// the full 65536-entry fp16 value window (128 KB) staged in dynamic smem,
// pixel gathers become LDS.
// ---------------------------------------------------------------------------
__global__ void __launch_bounds__(512) gather_kernel(
    const int* __restrict__ pix2cc, float* __restrict__ out)
{
    extern __shared__ __half sv[];
    const int row = blockIdx.x >> 3;                 // GSLICE = 8
    const int pbase = blockIdx.x << 15;              // 32768 pixels per block

    const uint4* vals = (const uint4*)(g_val + (row << 16));
    #pragma unroll
    for (int i = threadIdx.x; i < NC * 2 / 16; i += 512)
        ((uint4*)sv)[i] = __ldcg(&vals[i]);
    __syncthreads();

    const int4* pc = (const int4*)(pix2cc + pbase);
    float4* op = (float4*)(out + pbase);
    #pragma unroll
    for (int i = threadIdx.x; i < 32768 / 4; i += 512) {
        const int4 cc = __ldg(&pc[i]);
        float4 o;
        o.x = __half2float(sv[cc.x]);
        o.y = __half2float(sv[cc.y]);
        o.z = __half2float(sv[cc.z]);
        o.w = __half2float(sv[cc.w]);
        op[i] = o;
    }
}

// ---------------------------------------------------------------------------
extern "C" void kernel_launch(void* const* d_in, const int* in_sizes, int n_in,
                              void* d_out, int out_size) {
    const float* diff   = (const float*)d_in[0];
    const float* attrs  = (const float*)d_in[1];
    const float* weight = (const float*)d_in[2];
    const float* bias   = (const float*)d_in[3];
    const int*   parent = (const int*)d_in[4];
    const int*   pix2cc = (const int*)d_in[5];
    float* out = (float*)d_out;

    const int chunk_smem  = CK * 8;       // 64 KB
    const int gather_smem = NC * 2;       // 128 KB
    cudaFuncSetAttribute(chunk_kernel,
                         cudaFuncAttributeMaxDynamicSharedMemorySize, chunk_smem);
    cudaFuncSetAttribute(gather_kernel,
                         cudaFuncAttributeMaxDynamicSharedMemorySize, gather_smem);

    score_kernel<<<TOT / 256, 256>>>(diff, attrs, weight, bias, parent);
    chunk_kernel<<<TOT / CK, CT, chunk_smem>>>();
    extract_kernel<<<TOT / 1024, 256>>>();
    gather_kernel<<<NB * NN * GSLICE, 512, gather_smem>>>(pix2cc, out);
}